// round 4
// baseline (speedup 1.0000x reference)
#include <cuda_runtime.h>

// Problem constants
#define AP 48        // paths
#define LL 64        // length
#define DD 64        // channels
#define MM 63        // L-1 (increments)
#define PER_GRAM (AP*AP)          // 2304
#define NPAIRS (3*PER_GRAM)       // 6912

#define NBLK 96                   // 48 X path-blocks + 48 Y path-blocks
#define ROWS (NBLK*64)            // 6144 padded rows (row 63 of each block = 0)
#define NTILE 48                  // 6144 / 128 tiles per dim
#define NTRI (NTILE*(NTILE+1)/2)  // 1176 upper-triangle tiles

#define PDE_CTAS (NPAIRS / 8)     // 864 CTAs x 8 warps

// Static scratch (no allocation allowed)
__device__ float g_G[(size_t)ROWS * ROWS];         // big Gram (upper-tri tiles used)
__device__ float g_K[NPAIRS];
__device__ unsigned g_ctr;                          // last-CTA counter (reset by gemm)

// smem layout for gemm:
//   sAdup: [64 k][128 m] float2, each entry {a,a}, stride 129 (float2 units)
//          -> STS by consecutive k hits consecutive banks; LDS.64 is 2-addr bcast
//   sB   : [64 k][128 n] float,  stride 130 -> float2 reads 8B-aligned, conflict-free
#define ASTR 129
#define BSTR 130
#define SMEM_BYTES (64*ASTR*8 + 64*BSTR*4)   // 66048 + 33280 = 99328 B

// ---------------------------------------------------------------------------
// Kernel 1: G = dZ * dZ^T, 128x128x64 tiles, upper triangle (u >= t).
// Increments computed inline from X/Y (dz fused). 256 threads = 16x16;
// thread (ty,tx): rows 8*ty..+7 (blocked), col pairs {2*tx+32*j} (strided),
// packed fma.rn.f32x2 with pre-duplicated A operands (no pack movs).
// ---------------------------------------------------------------------------
__global__ void __launch_bounds__(256, 2) gemm_kernel(
    const float* __restrict__ X, const float* __restrict__ Y)
{
    extern __shared__ float smem[];
    float2* sAdup = reinterpret_cast<float2*>(smem);        // [k][m] duplicated
    float*  sB    = smem + 64 * ASTR * 2;                   // [k][n]

    if (blockIdx.x == 0 && threadIdx.x == 0) g_ctr = 0u;    // reset pde counter

    // decode triangular tile index -> (t, u), u >= t
    int q = blockIdx.x;
    int t = 0;
    while (q >= NTILE - t) { q -= NTILE - t; t++; }
    const int u = t + q;

    const int gr0 = t * 128;   // global row base (A side)
    const int gc0 = u * 128;   // global col base (B side)
    const int tid = threadIdx.x;

    // load tiles, computing increments inline. idx -> (m, k): consecutive tid
    // = consecutive k -> coalesced global reads of X/Y rows.
    for (int idx = tid; idx < 128 * 64; idx += 256) {
        const int m = idx >> 6;
        const int k = idx & 63;

        // A side: padded row gr0+m  ->  path block, position
        {
            const int row = gr0 + m;
            const int blk = row >> 6;
            const int i   = row & 63;
            float v = 0.0f;
            if (i < MM) {
                const float* src = (blk < AP) ? (X + blk * (LL * DD))
                                              : (Y + (blk - AP) * (LL * DD));
                v = src[(i + 1) * DD + k] - src[i * DD + k];
            }
            sAdup[k * ASTR + m] = make_float2(v, v);
        }
        // B side
        {
            const int row = gc0 + m;
            const int blk = row >> 6;
            const int i   = row & 63;
            float v = 0.0f;
            if (i < MM) {
                const float* src = (blk < AP) ? (X + blk * (LL * DD))
                                              : (Y + (blk - AP) * (LL * DD));
                v = src[(i + 1) * DD + k] - src[i * DD + k];
            }
            sB[k * BSTR + m] = v;
        }
    }
    __syncthreads();

    const int ty = tid >> 4;     // 0..15
    const int tx = tid & 15;     // 0..15
    const int m0 = ty * 8;
    const int n0 = 2 * tx;

    unsigned long long acc[8][4];
#pragma unroll
    for (int i = 0; i < 8; i++)
#pragma unroll
        for (int j = 0; j < 4; j++) acc[i][j] = 0ull;

    const float2* sA_ = sAdup + m0;
    const float*  sB_ = sB + n0;

#pragma unroll 8
    for (int k = 0; k < 64; k++) {
        unsigned long long aa[8], bb[4];
#pragma unroll
        for (int i = 0; i < 8; i++)
            aa[i] = *reinterpret_cast<const unsigned long long*>(
                        &sA_[k * ASTR + i]);
#pragma unroll
        for (int j = 0; j < 4; j++)
            bb[j] = *reinterpret_cast<const unsigned long long*>(
                        &sB_[k * BSTR + 32 * j]);
#pragma unroll
        for (int i = 0; i < 8; i++)
#pragma unroll
            for (int j = 0; j < 4; j++)
                asm("fma.rn.f32x2 %0, %1, %2, %0;"
                    : "+l"(acc[i][j]) : "l"(aa[i]), "l"(bb[j]));
    }

    // epilogue: bit-cast accumulators to float2, 16 lanes -> 128B contiguous
#pragma unroll
    for (int i = 0; i < 8; i++) {
        float* row = g_G + (size_t)(gr0 + m0 + i) * ROWS + gc0 + n0;
#pragma unroll
        for (int j = 0; j < 4; j++)
            *reinterpret_cast<float2*>(row + 32 * j) =
                *reinterpret_cast<float2*>(&acc[i][j]);
    }
}

// ---------------------------------------------------------------------------
// Kernel 2: Goursat PDE recursion (one warp per pair) + fused final reduction
// in the last-arriving CTA (threadfence + counter; deterministic sum order).
// Row update is a prefix sum: new[j+1] = 1 + sum_{k<=j} c[k],
//   c[j] = prev[j+1] + prev[j]*(inc[i,j]-1).
// ---------------------------------------------------------------------------
__global__ void __launch_bounds__(256) pde_kernel(
    const float* __restrict__ X, const float* __restrict__ Y,
    float* __restrict__ out)
{
    const int warp = (blockIdx.x * blockDim.x + threadIdx.x) >> 5;
    const int lane = threadIdx.x & 31;

    {
        const int p = warp;
        const int gram = p / PER_GRAM;
        const int r = p % PER_GRAM;
        const int a = r / AP, b = r % AP;

        if (gram < 2 && a > b) {            // mirrored pair handled via weight 2
            if (lane == 0) g_K[p] = 0.0f;
        } else {
            float w;
            int pa, pb;
            if (gram == 2)      { w = -2.0f / (float)PER_GRAM; pa = a;      pb = AP + b; }
            else if (gram == 1) { w = ((a == b) ? 1.0f : 2.0f) / (float)PER_GRAM;
                                  pa = AP + a; pb = AP + b; }
            else                { w = ((a == b) ? 1.0f : 2.0f) / (float)PER_GRAM;
                                  pa = a;      pb = b; }

            const float* __restrict__ base =
                g_G + (size_t)(64 * pa) * ROWS + 64 * pb + 2 * lane;
            const bool last = (lane == 31);

            float prev0 = 1.0f;   // K[i][2l]
            float prev1 = 1.0f;   // K[i][2l+1]

            float2 inc = __ldg(reinterpret_cast<const float2*>(base));

            for (int i = 0; i < MM; i++) {
                float2 nxt = make_float2(0.0f, 0.0f);
                if (i + 1 < MM)
                    nxt = __ldg(reinterpret_cast<const float2*>(
                                    base + (size_t)(i + 1) * ROWS));

                const float prev2 = __shfl_down_sync(0xffffffffu, prev0, 1);

                const float c0 = fmaf(prev0, inc.x - 1.0f, prev1);
                const float c1 = last ? 0.0f : fmaf(prev1, inc.y - 1.0f, prev2);

                const float s = c0 + c1;
                float tcum = s;
#pragma unroll
                for (int off = 1; off < 32; off <<= 1) {
                    const float uu = __shfl_up_sync(0xffffffffu, tcum, off);
                    if (lane >= off) tcum += uu;
                }
                const float E = tcum - s;     // exclusive scan of pair sums

                prev0 = 1.0f + E;             // new K[i+1][2l]
                prev1 = prev0 + c0;           // new K[i+1][2l+1]
                inc = nxt;
            }

            if (last) g_K[p] = w * prev1;     // K[63][63], weighted
        }
    }

    // ---- fused final reduction: last CTA to finish sums g_K + start term ----
    __shared__ bool s_is_last;
    __shared__ float sdata[256];

    __syncthreads();
    __threadfence();
    if (threadIdx.x == 0) {
        const unsigned old = atomicAdd(&g_ctr, 1u);
        s_is_last = (old == (unsigned)(gridDim.x - 1));
    }
    __syncthreads();
    if (!s_is_last) return;

    const int tid = threadIdx.x;
    float s = 0.0f;
    for (int p = tid; p < NPAIRS; p += 256) s += __ldcg(&g_K[p]);

    float s2 = 0.0f;
    for (int idx = tid; idx < AP * DD; idx += 256) {
        const int aa = idx >> 6;
        const int d  = idx & 63;
        const float diff = X[aa * (LL * DD) + d] - Y[aa * (LL * DD) + d];
        s2 = fmaf(diff, diff, s2);
    }
    s += s2 * (1.0f / (float)(AP * DD));

    sdata[tid] = s;
    __syncthreads();
    for (int k = 128; k > 0; k >>= 1) {
        if (tid < k) sdata[tid] += sdata[tid + k];
        __syncthreads();
    }
    if (tid == 0) out[0] = sdata[0];
}

// ---------------------------------------------------------------------------
extern "C" void kernel_launch(void* const* d_in, const int* in_sizes, int n_in,
                              void* d_out, int out_size)
{
    const float* X = (const float*)d_in[0];
    const float* Y = (const float*)d_in[1];
    float* out = (float*)d_out;

    static bool attr_done = false;
    if (!attr_done) {
        cudaFuncSetAttribute(gemm_kernel,
                             cudaFuncAttributeMaxDynamicSharedMemorySize,
                             SMEM_BYTES);
        attr_done = true;
    }

    gemm_kernel<<<NTRI, 256, SMEM_BYTES>>>(X, Y);
    pde_kernel<<<PDE_CTAS, 256>>>(X, Y, out);
}

// round 5
// speedup vs baseline: 1.0131x; 1.0131x over previous
#include <cuda_runtime.h>

// Problem constants
#define AP 48        // paths
#define LL 64        // length
#define DD 64        // channels
#define MM 63        // L-1 (increments)
#define PER_GRAM (AP*AP)          // 2304

#define NPB 96                    // 48 X path-blocks + 48 Y path-blocks (64 rows each)
#define NTILE 48                  // (96*64)/128 tiles per dim
#define NTRI (NTILE*(NTILE+1)/2)  // 1176 upper-triangle tiles
#define NK (NPB*NPB)              // 9216 pair slots

// Static scratch (no allocation allowed). Zero-initialized at module load;
// inactive g_K slots are never written and stay 0 forever (deterministic).
__device__ float g_K[NK];
__device__ unsigned g_ctr;        // last-CTA counter; reset by the last CTA

// smem layout:
//   phase 1 (mainloop): sAdup [64 k][128 m] float2 {a,a}, stride ASTR (float2)
//                       sB    [64 k][128 n] float,        stride BSTR
//   phase 2 (PDE):      sT    [128][TSTR] float tile (aliases phase-1 space)
#define ASTR 129
#define BSTR 130
#define TSTR 130
#define MAIN_FLOATS (64*ASTR*2 + 64*BSTR)      // 24832
#define TILE_FLOATS (128*TSTR)                 // 16640
#define SMEM_BYTES (MAIN_FLOATS * 4)           // 99328 B (covers both phases)

// ---------------------------------------------------------------------------
// Fused kernel: 128x128x64 Gram tile (upper triangle, u >= t) computed with
// packed fma.rn.f32x2, dumped to smem, then 4 warps run the Goursat PDE for
// the tile's 4 (or 3 on-diagonal) 64x64 pair blocks. Last CTA reduces.
// ---------------------------------------------------------------------------
__global__ void __launch_bounds__(256, 2) fused_kernel(
    const float* __restrict__ X, const float* __restrict__ Y,
    float* __restrict__ out)
{
    extern __shared__ float smem[];
    float2* sAdup = reinterpret_cast<float2*>(smem);        // [k][m] duplicated
    float*  sB    = smem + 64 * ASTR * 2;                   // [k][n]
    float*  sT    = smem;                                   // tile (phase 2)

    // decode triangular tile index -> (t, u), u >= t
    int q = blockIdx.x;
    int t = 0;
    while (q >= NTILE - t) { q -= NTILE - t; t++; }
    const int u = t + q;

    const int gr0 = t * 128;   // global row base (A side)
    const int gc0 = u * 128;   // global col base (B side)
    const int tid = threadIdx.x;
    const int lane = tid & 31;
    const int wid  = tid >> 5;

    // ---- phase 0: load tiles, computing increments inline -----------------
    for (int idx = tid; idx < 128 * 64; idx += 256) {
        const int m = idx >> 6;
        const int k = idx & 63;
        {   // A side
            const int row = gr0 + m;
            const int blk = row >> 6;
            const int i   = row & 63;
            float v = 0.0f;
            if (i < MM) {
                const float* src = (blk < AP) ? (X + blk * (LL * DD))
                                              : (Y + (blk - AP) * (LL * DD));
                v = src[(i + 1) * DD + k] - src[i * DD + k];
            }
            sAdup[k * ASTR + m] = make_float2(v, v);
        }
        {   // B side
            const int row = gc0 + m;
            const int blk = row >> 6;
            const int i   = row & 63;
            float v = 0.0f;
            if (i < MM) {
                const float* src = (blk < AP) ? (X + blk * (LL * DD))
                                              : (Y + (blk - AP) * (LL * DD));
                v = src[(i + 1) * DD + k] - src[i * DD + k];
            }
            sB[k * BSTR + m] = v;
        }
    }
    __syncthreads();

    // ---- phase 1: 128x128x64 mainloop, packed f32x2 -----------------------
    const int ty = tid >> 4;     // 0..15
    const int tx = tid & 15;     // 0..15
    const int m0 = ty * 8;
    const int n0 = 2 * tx;

    unsigned long long acc[8][4];
#pragma unroll
    for (int i = 0; i < 8; i++)
#pragma unroll
        for (int j = 0; j < 4; j++) acc[i][j] = 0ull;

    {
        const float2* sA_ = sAdup + m0;
        const float*  sB_ = sB + n0;
#pragma unroll 8
        for (int k = 0; k < 64; k++) {
            unsigned long long aa[8], bb[4];
#pragma unroll
            for (int i = 0; i < 8; i++)
                aa[i] = *reinterpret_cast<const unsigned long long*>(
                            &sA_[k * ASTR + i]);
#pragma unroll
            for (int j = 0; j < 4; j++)
                bb[j] = *reinterpret_cast<const unsigned long long*>(
                            &sB_[k * BSTR + 32 * j]);
#pragma unroll
            for (int i = 0; i < 8; i++)
#pragma unroll
                for (int j = 0; j < 4; j++)
                    asm("fma.rn.f32x2 %0, %1, %2, %0;"
                        : "+l"(acc[i][j]) : "l"(aa[i]), "l"(bb[j]));
        }
    }
    __syncthreads();   // everyone done reading smem before we overwrite it

    // ---- phase 2: dump tile to smem ---------------------------------------
#pragma unroll
    for (int i = 0; i < 8; i++) {
        float* row = sT + (m0 + i) * TSTR + n0;
#pragma unroll
        for (int j = 0; j < 4; j++)
            *reinterpret_cast<float2*>(row + 32 * j) =
                *reinterpret_cast<float2*>(&acc[i][j]);
    }
    __syncthreads();

    // ---- phase 3: Goursat PDE, warp w (0..3) -> sub-pair (r, c) -----------
    // Row update is a prefix sum: new[j+1] = 1 + sum_{k<=j} c[k],
    //   c[j] = prev[j+1] + prev[j]*(inc[i,j]-1).
    if (wid < 4) {
        const int r = wid >> 1, c = wid & 1;
        const int pa = 2 * t + r;
        const int pb = 2 * u + c;
        const bool active = !(t == u && r == 1 && c == 0);   // pa <= pb

        if (active) {
            float w;
            if (pa < AP && pb >= AP) w = -2.0f / (float)PER_GRAM;           // XY
            else                     w = ((pa == pb) ? 1.0f : 2.0f)
                                         / (float)PER_GRAM;                 // XX/YY

            const float* base = sT + (64 * r) * TSTR + 64 * c + 2 * lane;
            const bool lastl = (lane == 31);

            float prev0 = 1.0f;   // K[i][2l]
            float prev1 = 1.0f;   // K[i][2l+1]

            for (int i = 0; i < MM; i++) {
                const float2 inc =
                    *reinterpret_cast<const float2*>(base + i * TSTR);

                const float prev2 = __shfl_down_sync(0xffffffffu, prev0, 1);

                const float c0 = fmaf(prev0, inc.x - 1.0f, prev1);
                const float c1 = lastl ? 0.0f
                                       : fmaf(prev1, inc.y - 1.0f, prev2);

                const float s = c0 + c1;
                float tcum = s;
#pragma unroll
                for (int off = 1; off < 32; off <<= 1) {
                    const float uu = __shfl_up_sync(0xffffffffu, tcum, off);
                    if (lane >= off) tcum += uu;
                }
                const float E = tcum - s;     // exclusive scan of pair sums

                prev0 = 1.0f + E;             // new K[i+1][2l]
                prev1 = prev0 + c0;           // new K[i+1][2l+1]
            }

            if (lastl) g_K[pa * NPB + pb] = w * prev1;   // weighted K[63][63]
        }
    }

    // ---- phase 4: last CTA reduces ----------------------------------------
    __threadfence();
    __syncthreads();
    __shared__ bool s_is_last;
    if (tid == 0)
        s_is_last = (atomicAdd(&g_ctr, 1u) == (unsigned)(gridDim.x - 1));
    __syncthreads();
    if (!s_is_last) return;

    __shared__ float sdata[256];
    float s = 0.0f;
    for (int p = tid; p < NK; p += 256) s += __ldcg(&g_K[p]);

    float s2 = 0.0f;
    for (int idx = tid; idx < AP * DD; idx += 256) {
        const int aa = idx >> 6;
        const int d  = idx & 63;
        const float diff = X[aa * (LL * DD) + d] - Y[aa * (LL * DD) + d];
        s2 = fmaf(diff, diff, s2);
    }
    s += s2 * (1.0f / (float)(AP * DD));

    sdata[tid] = s;
    __syncthreads();
    for (int k = 128; k > 0; k >>= 1) {
        if (tid < k) sdata[tid] += sdata[tid + k];
        __syncthreads();
    }
    if (tid == 0) {
        out[0] = sdata[0];
        g_ctr = 0u;              // reset for the next graph replay
    }
}

// ---------------------------------------------------------------------------
extern "C" void kernel_launch(void* const* d_in, const int* in_sizes, int n_in,
                              void* d_out, int out_size)
{
    const float* X = (const float*)d_in[0];
    const float* Y = (const float*)d_in[1];
    float* out = (float*)d_out;

    static bool attr_done = false;
    if (!attr_done) {
        cudaFuncSetAttribute(fused_kernel,
                             cudaFuncAttributeMaxDynamicSharedMemorySize,
                             SMEM_BYTES);
        attr_done = true;
    }

    fused_kernel<<<NTRI, 256, SMEM_BYTES>>>(X, Y, out);
}